// round 4
// baseline (speedup 1.0000x reference)
#include <cuda_runtime.h>

#define N 512
#define ROWS_PER_BLOCK 4
#define NWARPS (N / 32)

// Closed form for the Givens-rotation chain (rotations on columns (i,i+1),
// applied for i = N-2 down to 0, theta index == i):
//   U[r][j]   = 0                                        for j > r+1
//   U[r][r+1] = s_r
//   U[r][j]   = c'_r * c_{j-1} * prod_{m=j}^{r-1} (-s_m) for j <= r
// with c_{-1} = 1 and c'_{N-1} = 1.
//
// Thread j of block b (rows r0..r0+3) needs T[j] = prod_{m=j}^{r0-1}(-s_m).
// Radix-4 warp suffix scan (3 shuffle rounds, shuffles within a round are
// independent) + broadcast-LDS combine of the 16 warp totals (no serial
// shuffle chain). ONE __syncthreads total.
__global__ __launch_bounds__(N) void unitary_closed_form_kernel(
    const float* __restrict__ thetas,  // K = N-1 = 511 angles
    float* __restrict__ out)           // N x N row-major fp32
{
    __shared__ float sh_s[N];                    // sin(theta_j), sh_s[N-1] = 0
    __shared__ float sh_c[N];                    // cos(theta_j), sh_c[N-1] = 1
    __shared__ __align__(16) float shW[NWARPS];  // per-warp product

    const int j    = threadIdx.x;
    const int lane = j & 31;
    const int w    = j >> 5;
    const int r0   = blockIdx.x * ROWS_PER_BLOCK;

    // Branch-free prologue: clamped load, fast sincos, fix up lane N-1.
    const int jc = (j < N - 1) ? j : (N - 2);
    float sj, cj;
    __sincosf(__ldg(thetas + jc), &sj, &cj);
    if (j == N - 1) { sj = 0.0f; cj = 1.0f; }
    sh_s[j] = sj;
    sh_c[j] = cj;

    // a[j] = -s_j for j < r0, else 1. Radix-4 suffix-product scan within warp:
    // after 3 rounds, p = prod_{m=j}^{warp_end} a_m.
    float p = (j < r0) ? -sj : 1.0f;
    {
        // Round 1: offsets 1,2,3 -> covers [lane, lane+3]
        float v1 = __shfl_down_sync(0xffffffffu, p, 1);
        float v2 = __shfl_down_sync(0xffffffffu, p, 2);
        float v3 = __shfl_down_sync(0xffffffffu, p, 3);
        if (lane + 1 >= 32) v1 = 1.0f;
        if (lane + 2 >= 32) v2 = 1.0f;
        if (lane + 3 >= 32) v3 = 1.0f;
        p = (p * v1) * (v2 * v3);
        // Round 2: offsets 4,8,12 -> covers [lane, lane+15]
        float u1 = __shfl_down_sync(0xffffffffu, p, 4);
        float u2 = __shfl_down_sync(0xffffffffu, p, 8);
        float u3 = __shfl_down_sync(0xffffffffu, p, 12);
        if (lane + 4 >= 32) u1 = 1.0f;
        if (lane + 8 >= 32) u2 = 1.0f;
        if (lane + 12 >= 32) u3 = 1.0f;
        p = (p * u1) * (u2 * u3);
        // Round 3: offset 16 -> covers [lane, 31]
        float t1 = __shfl_down_sync(0xffffffffu, p, 16);
        if (lane + 16 >= 32) t1 = 1.0f;
        p = p * t1;
    }
    if (lane == 0) shW[w] = p;   // full-warp product

    __syncthreads();   // covers sh_s, sh_c, shW

    // Broadcast-LDS combine: every thread reads all 16 warp totals (4x LDS.128,
    // conflict-free broadcast) and multiplies the ones with index > w.
    const float4* shW4 = reinterpret_cast<const float4*>(shW);
    float4 q0 = shW4[0], q1 = shW4[1], q2 = shW4[2], q3 = shW4[3];
    float g[NWARPS];
    g[0]=q0.x; g[1]=q0.y; g[2]=q0.z; g[3]=q0.w;
    g[4]=q1.x; g[5]=q1.y; g[6]=q1.z; g[7]=q1.w;
    g[8]=q2.x; g[9]=q2.y; g[10]=q2.z; g[11]=q2.w;
    g[12]=q3.x; g[13]=q3.y; g[14]=q3.z; g[15]=q3.w;
    #pragma unroll
    for (int m = 0; m < NWARPS; ++m)
        g[m] = (m > w) ? g[m] : 1.0f;
    #pragma unroll
    for (int st = 1; st < NWARPS; st <<= 1)
        #pragma unroll
        for (int i = 0; i < NWARPS; i += 2 * st)
            g[i] *= g[i + st];
    const float e = g[0];           // prod_{m=w+1}^{15} shW[m]

    const float T = p * e;          // prod_{m=j}^{r0-1} (-s_m)

    // Independent LDS, overlap with the combine above.
    const float cm1   = (j > 0) ? sh_c[j - 1] : 1.0f;
    const float sprev = (j > 0) ? sh_s[j - 1] : 0.0f;
    float cr[ROWS_PER_BLOCK], sr[ROWS_PER_BLOCK];
    #pragma unroll
    for (int k = 0; k < ROWS_PER_BLOCK; ++k) {
        cr[k] = sh_c[r0 + k];
        sr[k] = sh_s[r0 + k];
    }

    float x = cm1 * T;
    float* row = out + (size_t)r0 * N + j;
    #pragma unroll
    for (int k = 0; k < ROWS_PER_BLOCK; ++k) {
        const int r = r0 + k;
        float val;
        if (j <= r) {
            val = cr[k] * x;     // sh_c[N-1] == 1 handles r = N-1
            x *= -sr[k];         // sh_s[N-1] == 0, x unused afterwards
        } else if (j == r + 1) {
            val = sprev;         // superdiagonal: s_r
        } else {
            val = 0.0f;
        }
        row[0] = val;            // coalesced across j
        row += N;
    }
}

extern "C" void kernel_launch(void* const* d_in, const int* in_sizes, int n_in,
                              void* d_out, int out_size) {
    (void)in_sizes; (void)n_in; (void)out_size;
    const float* thetas = (const float*)d_in[0];
    float* out = (float*)d_out;
    unitary_closed_form_kernel<<<N / ROWS_PER_BLOCK, N>>>(thetas, out);
}